// round 2
// baseline (speedup 1.0000x reference)
#include <cuda_runtime.h>

#define TLEN 2048
#define BATCH 8192
#define STEPS 16                 // steps per pipelined tile
#define NT (TLEN / STEPS)        // 128 tiles

__device__ __forceinline__ float frcp_fast(float x) {
    float r;
    asm("rcp.approx.f32 %0, %1;" : "=f"(r) : "f"(x));
    return r;
}

__global__ void __launch_bounds__(32)
ekf_kernel(const float* __restrict__ price,
           const float* __restrict__ hurst,
           const float* __restrict__ sigv,
           float* __restrict__ out)
{
    const int b = blockIdx.x * blockDim.x + threadIdx.x;
    if (b >= BATCH) return;

    const float4* __restrict__ p4 = (const float4*)(price + (size_t)b * TLEN);
    const float4* __restrict__ h4 = (const float4*)(hurst + (size_t)b * TLEN);
    const float4* __restrict__ s4 = (const float4*)(sigv  + (size_t)b * TLEN);
    float4* __restrict__ o4 = (float4*)(out + (size_t)b * TLEN * 2);

    // ---- load tile 0 (4 float4 per input = 16 steps) ----
    float4 pc[4], hc[4], sc[4];
    #pragma unroll
    for (int i = 0; i < 4; i++) {
        pc[i] = p4[i];
        hc[i] = h4[i];
        sc[i] = s4[i];
    }

    // initial state: x = [z0, (z1 - z0)/dt], dt = 1; P = I
    float x0 = pc[0].x;
    float x1 = pc[0].y - pc[0].x;
    float p00 = 1.0f, p01 = 0.0f, p11 = 1.0f;

    #pragma unroll 1
    for (int tb = 0; tb < NT; tb++) {
        // ---- prefetch next tile: 12 independent LDG.128 front-batched (MLP ~12) ----
        const int nb = (tb + 1 < NT) ? (tb + 1) : tb;   // clamp: redundant reload on last tile
        float4 pn[4], hn[4], sn[4];
        #pragma unroll
        for (int i = 0; i < 4; i++) {
            pn[i] = p4[4 * nb + i];
            hn[i] = h4[4 * nb + i];
            sn[i] = s4[4 * nb + i];
        }

        // ---- compute 16 sequential EKF steps on the current tile ----
        #pragma unroll
        for (int i = 0; i < 4; i++) {
            const float zz[4] = {pc[i].x, pc[i].y, pc[i].z, pc[i].w};
            const float hh[4] = {hc[i].x, hc[i].y, hc[i].z, hc[i].w};
            const float ss[4] = {sc[i].x, sc[i].y, sc[i].z, sc[i].w};

            float ox[8];

            #pragma unroll
            for (int j = 0; j < 4; j++) {
                const float z  = zz[j];
                const float h  = hh[j];
                const float sg = ss[j];

                // rho = 0.5 + 0.5*sigmoid(10*(h-0.5)); a = dt*rho (dt=1)
                const float e = __expf(5.0f - 10.0f * h);
                const float a = fmaf(0.5f, frcp_fast(1.0f + e), 0.5f);

                // scale = max(100*sig, 1); q = 0.1*scale
                const float scale = fmaxf(100.0f * sg, 1.0f);
                const float q  = 0.1f * scale;
                const float qs = q + scale;               // off the carried chain

                // --- predict P (symmetric: p00, p01, p11) ---
                const float p01n = fmaf(a, p11, p01);
                const float tmp  = p01n + p01;
                const float S    = fmaf(a, tmp, p00 + qs); // = p00_pred + scale
                const float p00n = S - scale;              // runs parallel to rcp
                const float p11n = p11 + q;

                const float Sinv = frcp_fast(S);           // 1e-6 negligible (S >= 1)
                const float K0 = p00n * Sinv;
                const float K1 = p01n * Sinv;

                // --- predict/update x ---
                const float xp0 = fmaf(a, x1, x0);
                const float y   = z - xp0;
                x0 = fmaf(K0, y, xp0);
                x1 = fmaf(K1, y, x1);

                // --- update P ---
                p00 = fmaf(-K0, p00n, p00n);
                p01 = fmaf(-K0, p01n, p01n);
                p11 = fmaf(-K1, p01n, p11n);

                ox[2 * j + 0] = x0;
                ox[2 * j + 1] = x1;
            }

            float4 oA, oB;
            oA.x = ox[0]; oA.y = ox[1]; oA.z = ox[2]; oA.w = ox[3];
            oB.x = ox[4]; oB.y = ox[5]; oB.z = ox[6]; oB.w = ox[7];
            o4[8 * tb + 2 * i + 0] = oA;
            o4[8 * tb + 2 * i + 1] = oB;
        }

        // rotate buffers (register rename, free)
        #pragma unroll
        for (int i = 0; i < 4; i++) {
            pc[i] = pn[i];
            hc[i] = hn[i];
            sc[i] = sn[i];
        }
    }
}

extern "C" void kernel_launch(void* const* d_in, const int* in_sizes, int n_in,
                              void* d_out, int out_size)
{
    const float* price = (const float*)d_in[0];
    const float* hurst = (const float*)d_in[1];
    const float* sigv  = (const float*)d_in[2];
    float* out = (float*)d_out;

    // 8192 threads: 32-thread blocks x 256 blocks -> all 148 SMs active
    ekf_kernel<<<BATCH / 32, 32>>>(price, hurst, sigv, out);
}

// round 3
// speedup vs baseline: 1.8193x; 1.8193x over previous
#include <cuda_runtime.h>

#define TLEN  2048
#define BATCH 8192
#define STEPS 8
#define NT    (TLEN / STEPS)   // 256 tiles
#define RING  4                // smem ring depth (issue distance 3 tiles)

__device__ __forceinline__ float frcp_fast(float x) {
    float r;
    asm("rcp.approx.f32 %0, %1;" : "=f"(r) : "f"(x));
    return r;
}

__device__ __forceinline__ void cpasync16(float4* dst, const float4* src) {
    unsigned d = (unsigned)__cvta_generic_to_shared(dst);
    asm volatile("cp.async.cg.shared.global [%0], [%1], 16;" :: "r"(d), "l"(src) : "memory");
}

__device__ __forceinline__ void cp_commit() {
    asm volatile("cp.async.commit_group;" ::: "memory");
}

__global__ void __launch_bounds__(32)
ekf_kernel(const float* __restrict__ price,
           const float* __restrict__ hurst,
           const float* __restrict__ sigv,
           float* __restrict__ out)
{
    // ring buffer: [slot][input-chunk][lane]; 4*6*32*16 = 12 KB
    __shared__ float4 buf[RING][6][32];

    const int lane = threadIdx.x;
    const int b = blockIdx.x * 32 + lane;   // grid is exactly BATCH/32

    const float4* __restrict__ p4 = (const float4*)(price + (size_t)b * TLEN);
    const float4* __restrict__ h4 = (const float4*)(hurst + (size_t)b * TLEN);
    const float4* __restrict__ s4 = (const float4*)(sigv  + (size_t)b * TLEN);
    float4* __restrict__ o4 = (float4*)(out + (size_t)b * TLEN * 2);

    // ---- prologue: issue tiles 0..2 into slots 0..2 (one commit group each) ----
    #pragma unroll
    for (int t = 0; t < RING - 1; t++) {
        cpasync16(&buf[t][0][lane], p4 + 2 * t + 0);
        cpasync16(&buf[t][1][lane], p4 + 2 * t + 1);
        cpasync16(&buf[t][2][lane], h4 + 2 * t + 0);
        cpasync16(&buf[t][3][lane], h4 + 2 * t + 1);
        cpasync16(&buf[t][4][lane], s4 + 2 * t + 0);
        cpasync16(&buf[t][5][lane], s4 + 2 * t + 1);
        cp_commit();
    }

    // initial state (scalar LDG, overlapped with prologue cp.asyncs)
    const float z0 = price[(size_t)b * TLEN + 0];
    const float z1 = price[(size_t)b * TLEN + 1];
    float x0 = z0;
    float x1 = z1 - z0;            // dt = 1
    float p00 = 1.0f, p01 = 0.0f, p11 = 1.0f;

    #pragma unroll 1
    for (int t = 0; t < NT; t++) {
        // issue tile t+3 (clamped at the tail -> constant group count, safe slot reuse)
        {
            const int nt_  = t + RING - 1;
            const int tc   = (nt_ < NT) ? nt_ : (NT - 1);
            const int slot = nt_ & (RING - 1);
            cpasync16(&buf[slot][0][lane], p4 + 2 * tc + 0);
            cpasync16(&buf[slot][1][lane], p4 + 2 * tc + 1);
            cpasync16(&buf[slot][2][lane], h4 + 2 * tc + 0);
            cpasync16(&buf[slot][3][lane], h4 + 2 * tc + 1);
            cpasync16(&buf[slot][4][lane], s4 + 2 * tc + 0);
            cpasync16(&buf[slot][5][lane], s4 + 2 * tc + 1);
            cp_commit();
        }
        // <=3 groups pending  ==>  tile t's group has landed
        asm volatile("cp.async.wait_group 3;" ::: "memory");

        const int slot = t & (RING - 1);
        const float4 pv0 = buf[slot][0][lane];
        const float4 pv1 = buf[slot][1][lane];
        const float4 hv0 = buf[slot][2][lane];
        const float4 hv1 = buf[slot][3][lane];
        const float4 sv0 = buf[slot][4][lane];
        const float4 sv1 = buf[slot][5][lane];

        const float zz[8] = {pv0.x, pv0.y, pv0.z, pv0.w, pv1.x, pv1.y, pv1.z, pv1.w};
        const float hh[8] = {hv0.x, hv0.y, hv0.z, hv0.w, hv1.x, hv1.y, hv1.z, hv1.w};
        const float ss[8] = {sv0.x, sv0.y, sv0.z, sv0.w, sv1.x, sv1.y, sv1.z, sv1.w};

        float ox[16];

        #pragma unroll
        for (int j = 0; j < STEPS; j++) {
            const float z  = zz[j];
            const float h  = hh[j];
            const float sg = ss[j];

            // rho = 0.5 + 0.5*sigmoid(10*(h-0.5)); a = dt*rho (dt=1)  [off-chain]
            const float e = __expf(5.0f - 10.0f * h);
            const float a = fmaf(0.5f, frcp_fast(1.0f + e), 0.5f);

            // scale = max(100*sig, 1); q = 0.1*scale                 [off-chain]
            const float scale = fmaxf(100.0f * sg, 1.0f);
            const float q  = 0.1f * scale;
            const float qs = q + scale;

            // --- predict P (symmetric: p00, p01, p11) ---
            const float p01n = fmaf(a, p11, p01);
            const float tmp  = p01n + p01;
            const float S    = fmaf(a, tmp, p00 + qs);  // = p00_pred + scale
            const float p00n = S - scale;               // parallel with rcp
            const float p11n = p11 + q;

            const float Sinv = frcp_fast(S);            // 1e-6 negligible (S >= 1)
            const float K0 = p00n * Sinv;
            const float K1 = p01n * Sinv;

            // --- predict/update x ---
            const float xp0 = fmaf(a, x1, x0);
            const float y   = z - xp0;
            x0 = fmaf(K0, y, xp0);
            x1 = fmaf(K1, y, x1);

            // --- update P ---
            p00 = fmaf(-K0, p00n, p00n);
            p01 = fmaf(-K0, p01n, p01n);
            p11 = fmaf(-K1, p01n, p11n);

            ox[2 * j + 0] = x0;
            ox[2 * j + 1] = x1;
        }

        // 4 x STG.128 per tile
        #pragma unroll
        for (int i = 0; i < 4; i++) {
            float4 o;
            o.x = ox[4 * i + 0];
            o.y = ox[4 * i + 1];
            o.z = ox[4 * i + 2];
            o.w = ox[4 * i + 3];
            o4[4 * t + i] = o;
        }
    }
}

extern "C" void kernel_launch(void* const* d_in, const int* in_sizes, int n_in,
                              void* d_out, int out_size)
{
    const float* price = (const float*)d_in[0];
    const float* hurst = (const float*)d_in[1];
    const float* sigv  = (const float*)d_in[2];
    float* out = (float*)d_out;

    ekf_kernel<<<BATCH / 32, 32>>>(price, hurst, sigv, out);
}

// round 4
// speedup vs baseline: 1.8472x; 1.0153x over previous
#include <cuda_runtime.h>

#define TLEN  2048
#define BATCH 8192
#define STEPS 8
#define NT    (TLEN / STEPS)   // 256 tiles
#define RING  6                // smem ring depth

__device__ __forceinline__ float frcp_fast(float x) {
    float r;
    asm("rcp.approx.f32 %0, %1;" : "=f"(r) : "f"(x));
    return r;
}

__device__ __forceinline__ void cpasync16(float4* dst, const float4* src) {
    unsigned d = (unsigned)__cvta_generic_to_shared(dst);
    asm volatile("cp.async.cg.shared.global [%0], [%1], 16;" :: "r"(d), "l"(src) : "memory");
}
__device__ __forceinline__ void cp_commit() {
    asm volatile("cp.async.commit_group;" ::: "memory");
}
__device__ __forceinline__ void cp_wait4() {
    asm volatile("cp.async.wait_group 4;" ::: "memory");
}

// per-tile precomputed transform (state-independent)
struct T8 {
    float a[STEPS], q[STEPS], r[STEPS], r2[STEPS], qs[STEPS], z[STEPS];
};

__shared__ float4 g_buf[RING][6][32];

__device__ __forceinline__ void issue_tile(int tile, int slot, int lane,
                                           const float4* p4, const float4* h4, const float4* s4)
{
    cpasync16(&g_buf[slot][0][lane], p4 + 2 * tile + 0);
    cpasync16(&g_buf[slot][1][lane], p4 + 2 * tile + 1);
    cpasync16(&g_buf[slot][2][lane], h4 + 2 * tile + 0);
    cpasync16(&g_buf[slot][3][lane], h4 + 2 * tile + 1);
    cpasync16(&g_buf[slot][4][lane], s4 + 2 * tile + 0);
    cpasync16(&g_buf[slot][5][lane], s4 + 2 * tile + 1);
    cp_commit();
}

// read smem slot, compute transform arrays (all off the carried chain)
__device__ __forceinline__ void xform(int slot, int lane, T8& o)
{
    const float4 pv0 = g_buf[slot][0][lane];
    const float4 pv1 = g_buf[slot][1][lane];
    const float4 hv0 = g_buf[slot][2][lane];
    const float4 hv1 = g_buf[slot][3][lane];
    const float4 sv0 = g_buf[slot][4][lane];
    const float4 sv1 = g_buf[slot][5][lane];

    const float zz[8] = {pv0.x, pv0.y, pv0.z, pv0.w, pv1.x, pv1.y, pv1.z, pv1.w};
    const float hh[8] = {hv0.x, hv0.y, hv0.z, hv0.w, hv1.x, hv1.y, hv1.z, hv1.w};
    const float ss[8] = {sv0.x, sv0.y, sv0.z, sv0.w, sv1.x, sv1.y, sv1.z, sv1.w};

    #pragma unroll
    for (int j = 0; j < STEPS; j++) {
        const float e = __expf(5.0f - 10.0f * hh[j]);          // EX2
        const float a = fmaf(0.5f, frcp_fast(1.0f + e), 0.5f); // sigmoid
        const float r = fmaxf(100.0f * ss[j], 1.0f);
        const float q = 0.1f * r;
        o.a[j]  = a;
        o.q[j]  = q;
        o.r[j]  = r;
        o.r2[j] = r * r;
        o.qs[j] = q + r;
        o.z[j]  = zz[j];
    }
}

// 8 EKF steps; carried chain: S@12 -> rcp@28 -> {p00,p01,p11,K}@32
__device__ __forceinline__ void chain8(const T8& C,
                                       float& p00, float& p01, float& p11,
                                       float& x0, float& x1,
                                       float4* o4)
{
    float ox[16];
    #pragma unroll
    for (int j = 0; j < STEPS; j++) {
        const float a  = C.a[j];
        const float p01n = fmaf(a, p11, p01);
        const float X    = fmaf(a, p01, p00 + C.qs[j]);
        const float S    = fmaf(a, p01n, X);           // = P_pred00 + scale (+q folded)
        const float Sinv = frcp_fast(S);               // 1e-6 negligible (S >= 1)

        // off-chain products, computed in the rcp shadow
        const float rm   = p01n * C.r[j];
        const float n2   = p01n * p01n;
        const float p11n = p11 + C.q[j];
        const float xp0  = fmaf(a, x1, x0);
        const float y    = C.z[j] - xp0;

        const float K0 = fmaf(-C.r[j], Sinv, 1.0f);    // 1 - r/S
        const float K1 = p01n * Sinv;

        p00 = fmaf(-C.r2[j], Sinv, C.r[j]);            // r - r^2/S
        p01 = rm * Sinv;                               // r*p01n/S
        p11 = fmaf(-n2, Sinv, p11n);                   // p11n - p01n^2/S
        x0  = fmaf(K0, y, xp0);
        x1  = fmaf(K1, y, x1);

        ox[2 * j + 0] = x0;
        ox[2 * j + 1] = x1;
    }
    #pragma unroll
    for (int i = 0; i < 4; i++) {
        float4 o;
        o.x = ox[4 * i + 0];
        o.y = ox[4 * i + 1];
        o.z = ox[4 * i + 2];
        o.w = ox[4 * i + 3];
        o4[i] = o;
    }
}

__global__ void __launch_bounds__(32)
ekf_kernel(const float* __restrict__ price,
           const float* __restrict__ hurst,
           const float* __restrict__ sigv,
           float* __restrict__ out)
{
    const int lane = threadIdx.x;
    const int b = blockIdx.x * 32 + lane;

    const float4* __restrict__ p4 = (const float4*)(price + (size_t)b * TLEN);
    const float4* __restrict__ h4 = (const float4*)(hurst + (size_t)b * TLEN);
    const float4* __restrict__ s4 = (const float4*)(sigv  + (size_t)b * TLEN);
    float4* __restrict__ o4 = (float4*)(out + (size_t)b * TLEN * 2);

    // prologue: issue tiles 0..4 (5 groups), wait so tile 0 is resident
    #pragma unroll
    for (int t = 0; t < RING - 1; t++)
        issue_tile(t, t, lane, p4, h4, s4);
    cp_wait4();

    T8 A, B;
    xform(0, lane, A);

    // initial state from tile 0 (dt = 1)
    float x0 = A.z[0];
    float x1 = A.z[1] - A.z[0];
    float p00 = 1.0f, p01 = 0.0f, p11 = 1.0f;

    // ping-pong over tile pairs; NT = 256 (even)
    #pragma unroll 1
    for (int t = 0; t < NT; t += 2) {
        // ---- body A: chain on A, prefetch+transform t+1 into B ----
        {
            const int it = t + RING - 1;
            issue_tile((it < NT) ? it : (NT - 1), it % RING, lane, p4, h4, s4);
            cp_wait4();                        // tile t+1 resident
            xform((t + 1) % RING, lane, B);    // fills A-chain stall slots
            chain8(A, p00, p01, p11, x0, x1, o4 + 4 * t);
        }
        // ---- body B: chain on B, prefetch+transform t+2 into A ----
        {
            const int it = t + RING;
            issue_tile((it < NT) ? it : (NT - 1), it % RING, lane, p4, h4, s4);
            cp_wait4();                        // tile t+2 resident
            const int xt = (t + 2 < NT) ? (t + 2) : (NT - 1);
            xform(xt % RING, lane, A);
            chain8(B, p00, p01, p11, x0, x1, o4 + 4 * (t + 1));
        }
    }
}

extern "C" void kernel_launch(void* const* d_in, const int* in_sizes, int n_in,
                              void* d_out, int out_size)
{
    const float* price = (const float*)d_in[0];
    const float* hurst = (const float*)d_in[1];
    const float* sigv  = (const float*)d_in[2];
    float* out = (float*)d_out;

    ekf_kernel<<<BATCH / 32, 32>>>(price, hurst, sigv, out);
}